// round 1
// baseline (speedup 1.0000x reference)
#include <cuda_runtime.h>
#include <math.h>
#include <float.h>

#define TT 5
#define CC 3
#define HH 384
#define WW 384
#define PS 7
#define KK 10
#define NHH 96
#define NWW 96
#define NQ (TT*NHH*NWW)      /* 46080 */
#define NDI 3
#define NCAND (NDI*81)       /* 243 */

#define WPB 4                /* warps (queries) per block */
#define RSTRIDE 17           /* region row stride in floats (bank-conflict pad) */

__device__ double g_accum;

__global__ void init_kernel() { g_accum = 0.0; }

__global__ void finalize_kernel(float* out, int n) {
    double mean = g_accum / ((double)NQ * (double)KK);
    int i = blockIdx.x * blockDim.x + threadIdx.x;
    if (i < n) out[i] = (float)mean;
}

__global__ __launch_bounds__(128)
void search_kernel(const float* __restrict__ vid,
                   const float* __restrict__ fflow,
                   const float* __restrict__ bflow) {
    // per-warp scratch
    __shared__ float s_region[WPB][NDI*CC*15*RSTRIDE]; // 3*3*15 rows x 17
    __shared__ float s_q[WPB][152];
    __shared__ float s_dists[WPB][256];
    __shared__ int   s_meta[WPB][16]; // per di: tj, ystart, xstart, bh, bw

    const int warp = threadIdx.x >> 5;
    const int lane = threadIdx.x & 31;
    const int qidx = blockIdx.x * WPB + warp;
    if (qidx >= NQ) return;

    const int ti = qidx / (NHH * NWW);
    const int rr = qidx - ti * (NHH * NWW);
    const int hi = (rr / NWW) * 4;
    const int wi = (rr % NWW) * 4;

    float* region = s_region[warp];
    float* q      = s_q[warp];
    float* dists  = s_dists[warp];
    int*   meta   = s_meta[warp];

    // ---- meta per temporal offset di (0: t-1/bflow, 1: t/zero, 2: t+1/fflow) ----
    if (lane < 3) {
        int di = lane;
        int tj, bh, bw;
        if (di == 1) { tj = ti; bh = hi; bw = wi; }
        else {
            const float* fl = (di == 0) ? bflow : fflow;
            tj = (di == 0) ? max(ti - 1, 0) : min(ti + 1, TT - 1);
            float fx = fl[((ti*2 + 0)*HH + hi)*WW + wi];
            float fy = fl[((ti*2 + 1)*HH + hi)*WW + wi];
            bh = min(max(hi + (int)rintf(fy), 0), HH - 1);
            bw = min(max(wi + (int)rintf(fx), 0), WW - 1);
        }
        meta[di*5 + 0] = tj;
        meta[di*5 + 1] = max(bh - 4, 0);   // ystart
        meta[di*5 + 2] = max(bw - 4, 0);   // xstart
        meta[di*5 + 3] = bh;
        meta[di*5 + 4] = bw;
    }
    __syncwarp();

    // ---- query patch (147 floats), edge clamped ----
    for (int e = lane; e < CC*PS*PS; e += 32) {
        int c = e / 49; int r2 = e - c*49; int py = r2 / 7; int px = r2 - py*7;
        int y = min(hi + py, HH - 1);
        int x = min(wi + px, WW - 1);
        q[e] = vid[((ti*CC + c)*HH + y)*WW + x];
    }

    // ---- load 3 regions of 15x15x3 (row-saturated at H-1/W-1) ----
    for (int e = lane; e < NDI*CC*15*15; e += 32) {
        int di = e / 675; int r1 = e - di*675;
        int c  = r1 / 225; int r2 = r1 - c*225;
        int ry = r2 / 15;  int rx = r2 - ry*15;
        int tj = meta[di*5 + 0];
        int y  = min(meta[di*5 + 1] + ry, HH - 1);
        int x  = min(meta[di*5 + 2] + rx, WW - 1);
        region[((di*CC + c)*15 + ry)*RSTRIDE + rx] =
            vid[((tj*CC + c)*HH + y)*WW + x];
    }
    __syncwarp();

    // ---- compute: lane = (di, sy); 9 sx candidates per lane ----
    if (lane < 27) {
        int di = lane / 9;
        int sy = lane - di*9;
        int ys = meta[di*5 + 1];
        int xs = meta[di*5 + 2];
        int bh = meta[di*5 + 3];
        int bw = meta[di*5 + 4];
        int rowoff = min(max(bh - 4 + sy, 0), HH - 1) - ys;

        float acc[9];
        #pragma unroll
        for (int i = 0; i < 9; i++) acc[i] = 0.f;

        const float* regdi = region + di*CC*15*RSTRIDE;
        bool fastx = (bw >= 4) && (bw <= WW - 11);

        if (fastx) {
            #pragma unroll
            for (int c = 0; c < 3; c++) {
                #pragma unroll
                for (int py = 0; py < 7; py++) {
                    const float* row = regdi + (c*15 + rowoff + py)*RSTRIDE;
                    float v[15];
                    #pragma unroll
                    for (int j = 0; j < 15; j++) v[j] = row[j];
                    float qv[7];
                    #pragma unroll
                    for (int j = 0; j < 7; j++) qv[j] = q[c*49 + py*7 + j];
                    #pragma unroll
                    for (int sx = 0; sx < 9; sx++) {
                        #pragma unroll
                        for (int px = 0; px < 7; px++) {
                            float t = qv[px] - v[sx + px];
                            acc[sx] = fmaf(t, t, acc[sx]);
                        }
                    }
                }
            }
        } else {
            // rare border-in-x path: direct smem addressing with per-sx col offset
            #pragma unroll
            for (int sx = 0; sx < 9; sx++) {
                int co = min(max(bw - 4 + sx, 0), WW - 1) - xs;
                for (int c = 0; c < 3; c++) {
                    for (int py = 0; py < 7; py++) {
                        const float* row = regdi + (c*15 + rowoff + py)*RSTRIDE + co;
                        const float* qr  = q + c*49 + py*7;
                        #pragma unroll
                        for (int px = 0; px < 7; px++) {
                            float t = qr[px] - row[px];
                            acc[sx] = fmaf(t, t, acc[sx]);
                        }
                    }
                }
            }
        }

        #pragma unroll
        for (int sx = 0; sx < 9; sx++) dists[lane*9 + sx] = acc[sx];
    }
    // pad 243..255 with +inf
    for (int k = 243 + lane; k < 256; k += 32) dists[k] = FLT_MAX;
    __syncwarp();

    // ---- top-K (10 smallest): 10x extract-min over 256 padded slots ----
    float sumK = 0.f;
    for (int k = 0; k < KK; k++) {
        float mv = FLT_MAX; int mi = lane;
        #pragma unroll
        for (int j = 0; j < 8; j++) {
            int idx = lane + j*32;
            float v = dists[idx];
            if (v < mv) { mv = v; mi = idx; }
        }
        #pragma unroll
        for (int off = 16; off > 0; off >>= 1) {
            float ov = __shfl_down_sync(0xffffffffu, mv, off);
            int   oi = __shfl_down_sync(0xffffffffu, mi, off);
            if (ov < mv) { mv = ov; mi = oi; }
        }
        if (lane == 0) {
            sumK += mv;
            dists[mi] = FLT_MAX;
        }
        __syncwarp();
    }
    if (lane == 0) atomicAdd(&g_accum, (double)sumK);
}

extern "C" void kernel_launch(void* const* d_in, const int* in_sizes, int n_in,
                              void* d_out, int out_size) {
    const float* noisy = (const float*)d_in[0];
    // d_in[1] = deno (unused: SEARCH_INPUT='noisy' and refine reads noisy)
    const float* fflow = (const float*)d_in[2];
    const float* bflow = (const float*)d_in[3];
    float* out = (float*)d_out;

    init_kernel<<<1, 1>>>();
    search_kernel<<<NQ / WPB, 32 * WPB>>>(noisy, fflow, bflow);
    finalize_kernel<<<(out_size + 127) / 128, 128>>>(out, out_size);
}

// round 2
// speedup vs baseline: 1.0376x; 1.0376x over previous
#include <cuda_runtime.h>
#include <math.h>
#include <float.h>

#define TT 5
#define CC 3
#define HH 384
#define WW 384
#define KK 10
#define NHH 96
#define NWW 96
#define NQ (TT*NHH*NWW)      /* 46080 */
#define WPB 4                /* warps (queries) per block */
#define RSTR 18              /* region row stride in floats (even -> LDS.64 aligned) */
#define QSTR 8               /* query row stride (7 + zero pad) */

typedef unsigned long long u64;

__device__ double       g_accum;  /* zero-init at module load; self-reset each run */
__device__ unsigned int g_count;

__device__ __forceinline__ u64 pk2(float lo, float hi) {
    u64 r; asm("mov.b64 %0, {%1, %2};" : "=l"(r) : "f"(lo), "f"(hi)); return r;
}
__device__ __forceinline__ void upk2(u64 v, float& lo, float& hi) {
    asm("mov.b64 {%0, %1}, %2;" : "=f"(lo), "=f"(hi) : "l"(v));
}
__device__ __forceinline__ void fma2(u64& d, u64 a, u64 b) {
    asm("fma.rn.f32x2 %0, %1, %2, %0;" : "+l"(d) : "l"(a), "l"(b));
}

__global__ void __launch_bounds__(32*WPB)
fused_kernel(const float* __restrict__ vid,
             const float* __restrict__ fflow,
             const float* __restrict__ bflow,
             float* __restrict__ out, int out_size)
{
    __shared__ float s_region[WPB][3*3*15*RSTR];   /* 9720B / warp */
    __shared__ float s_q[WPB][3*7*QSTR];
    __shared__ int   s_meta[WPB][16];              /* per di: tj, ystart, xstart, bh, bw */

    const int warp = threadIdx.x >> 5;
    const int lane = threadIdx.x & 31;
    const int qidx = blockIdx.x * WPB + warp;

    const int ti = qidx / (NHH * NWW);
    const int rr = qidx - ti * (NHH * NWW);
    const int hi = (rr / NWW) * 4;
    const int wi = (rr % NWW) * 4;

    float* region = s_region[warp];
    float* q      = s_q[warp];
    int*   meta   = s_meta[warp];

    /* ---- meta per temporal offset di (0: t-1/bflow, 1: t/zero, 2: t+1/fflow) ---- */
    if (lane < 3) {
        int di = lane;
        int tj, bh, bw;
        if (di == 1) { tj = ti; bh = hi; bw = wi; }
        else {
            const float* fl = (di == 0) ? bflow : fflow;
            tj = (di == 0) ? max(ti - 1, 0) : min(ti + 1, TT - 1);
            float fx = fl[((ti*2 + 0)*HH + hi)*WW + wi];
            float fy = fl[((ti*2 + 1)*HH + hi)*WW + wi];
            bh = min(max(hi + (int)rintf(fy), 0), HH - 1);
            bw = min(max(wi + (int)rintf(fx), 0), WW - 1);
        }
        meta[di*5 + 0] = tj;
        meta[di*5 + 1] = max(bh - 4, 0);   /* ystart */
        meta[di*5 + 2] = max(bw - 4, 0);   /* xstart */
        meta[di*5 + 3] = bh;
        meta[di*5 + 4] = bw;
    }
    __syncwarp();

    /* ---- query patch, padded rows of 8 (last elem = 0) ---- */
    for (int e = lane; e < 3*7*QSTR; e += 32) {
        int c = e / (7*QSTR); int r2 = e - c*(7*QSTR);
        int py = r2 / QSTR;   int px = r2 - py*QSTR;
        float val = 0.f;
        if (px < 7) {
            int y = min(hi + py, HH - 1);
            int x = min(wi + px, WW - 1);
            val = vid[((ti*CC + c)*HH + y)*WW + x];
        }
        q[e] = val;
    }

    /* ---- 3 regions of 15 rows x 16 cols x 3c (row/col saturated) ---- */
    for (int e = lane; e < 3*3*15*16; e += 32) {
        int di = e / 720; int r1 = e - di*720;
        int c  = r1 / 240; int r2 = r1 - c*240;
        int ry = r2 >> 4;  int rx = r2 & 15;
        int tj = meta[di*5 + 0];
        int y  = min(meta[di*5 + 1] + ry, HH - 1);
        int x  = min(meta[di*5 + 2] + rx, WW - 1);
        region[((di*3 + c)*15 + ry)*RSTR + rx] =
            vid[((tj*CC + c)*HH + y)*WW + x];
    }
    __syncwarp();

    float d[9];
    #pragma unroll
    for (int j = 0; j < 9; j++) d[j] = FLT_MAX;

    if (lane < 27) {
        int di = lane / 9, sy = lane - di*9;
        int ys = meta[di*5 + 1], xs = meta[di*5 + 2];
        int bh = meta[di*5 + 3], bw = meta[di*5 + 4];
        int rowoff = min(max(bh - 4 + sy, 0), HH - 1) - ys;
        const float* regdi = region + di*3*15*RSTR;
        bool fastx = (bw >= 4) && (bw <= WW - 11);

        if (fastx) {
            /* SSD: d = qsq + vsq - 2*qv, packed f32x2 over px pairs */
            u64 acc[9], sq2[8], qsq2;
            const u64 z = pk2(0.f, 0.f);
            #pragma unroll
            for (int s = 0; s < 9; s++) acc[s] = z;
            #pragma unroll
            for (int p = 0; p < 8; p++) sq2[p] = z;
            qsq2 = z;

            #pragma unroll
            for (int c = 0; c < 3; c++) {
                #pragma unroll
                for (int py = 0; py < 7; py++) {
                    const float2* row = (const float2*)(regdi + (c*15 + rowoff + py)*RSTR);
                    const float2* qr  = (const float2*)(q + (c*7 + py)*QSTR);
                    float2 vf[8]; u64 ve[8];
                    #pragma unroll
                    for (int p = 0; p < 8; p++) { vf[p] = row[p]; ve[p] = pk2(vf[p].x, vf[p].y); }
                    u64 vo[7];
                    #pragma unroll
                    for (int p = 0; p < 7; p++) vo[p] = pk2(vf[p].y, vf[p+1].x);
                    u64 qp[4];
                    #pragma unroll
                    for (int j = 0; j < 4; j++) { float2 t = qr[j]; qp[j] = pk2(t.x, t.y); }

                    #pragma unroll
                    for (int j = 0; j < 4; j++) {
                        fma2(qsq2, qp[j], qp[j]);
                        #pragma unroll
                        for (int e2 = 0; e2 < 5; e2++)       /* sx = 0,2,4,6,8 */
                            fma2(acc[2*e2], qp[j], ve[e2 + j]);
                        #pragma unroll
                        for (int o = 0; o < 4; o++)          /* sx = 1,3,5,7 */
                            fma2(acc[2*o + 1], qp[j], vo[o + j]);
                    }
                    #pragma unroll
                    for (int p = 0; p < 8; p++) fma2(sq2[p], ve[p], ve[p]);
                }
            }

            /* epilogue: prefix-sum sliding window for vsq */
            float col[15];
            {
                float lo, hiv;
                #pragma unroll
                for (int p = 0; p < 7; p++) { upk2(sq2[p], lo, hiv); col[2*p] = lo; col[2*p+1] = hiv; }
                upk2(sq2[7], lo, hiv); col[14] = lo;
            }
            float pre[16]; pre[0] = 0.f;
            #pragma unroll
            for (int j = 0; j < 15; j++) pre[j+1] = pre[j] + col[j];
            float qlo, qhi; upk2(qsq2, qlo, qhi);
            float qs = qlo + qhi;
            #pragma unroll
            for (int sx = 0; sx < 9; sx++) {
                float alo, ahi; upk2(acc[sx], alo, ahi);
                float qv = alo + ahi;
                float vs = pre[sx+7] - pre[sx];
                d[sx] = fmaf(-2.f, qv, qs + vs);
            }
        } else {
            /* rare x-border path: direct scalar SSD with per-sx clamped col offset */
            #pragma unroll
            for (int sx = 0; sx < 9; sx++) {
                int co = min(max(bw - 4 + sx, 0), WW - 1) - xs;
                float a = 0.f;
                for (int c = 0; c < 3; c++) {
                    for (int py = 0; py < 7; py++) {
                        const float* row = regdi + (c*15 + rowoff + py)*RSTR + co;
                        const float* qr  = q + (c*7 + py)*QSTR;
                        #pragma unroll
                        for (int px = 0; px < 7; px++) {
                            float t = qr[px] - row[px];
                            a = fmaf(t, t, a);
                        }
                    }
                }
                d[sx] = a;
            }
        }
    }

    /* ---- register-resident top-10 (tie-aware extract-min) ---- */
    float sumK = 0.f;
    int need = KK;
    while (need > 0) {
        float m = d[0];
        #pragma unroll
        for (int j = 1; j < 9; j++) m = fminf(m, d[j]);
        #pragma unroll
        for (int off = 16; off; off >>= 1)
            m = fminf(m, __shfl_xor_sync(0xffffffffu, m, off));
        unsigned cnt = 0;
        #pragma unroll
        for (int j = 0; j < 9; j++)
            if (d[j] == m) { d[j] = FLT_MAX; cnt++; }
        unsigned tot = __reduce_add_sync(0xffffffffu, cnt);
        int take = min((int)tot, need);
        sumK += m * (float)take;
        need -= take;
    }
    if (lane == 0) atomicAdd(&g_accum, (double)sumK);

    /* ---- last-block finalize + reset (single-launch, graph-safe) ---- */
    __threadfence();
    __syncthreads();
    if (threadIdx.x == 0) {
        unsigned prev = atomicAdd(&g_count, 1u);
        if (prev == gridDim.x - 1) {
            double s = atomicAdd(&g_accum, 0.0);
            float mean = (float)(s / ((double)NQ * (double)KK));
            for (int i = 0; i < out_size; i++) out[i] = mean;
            g_count = 0u;
            g_accum = 0.0;
            __threadfence();
        }
    }
}

extern "C" void kernel_launch(void* const* d_in, const int* in_sizes, int n_in,
                              void* d_out, int out_size) {
    const float* noisy = (const float*)d_in[0];
    /* d_in[1] = deno: dead (SEARCH_INPUT='noisy', refine reads noisy) */
    const float* fflow = (const float*)d_in[2];
    const float* bflow = (const float*)d_in[3];
    float* out = (float*)d_out;

    fused_kernel<<<NQ / WPB, 32 * WPB>>>(noisy, fflow, bflow, out, out_size);
}

// round 3
// speedup vs baseline: 1.1010x; 1.0611x over previous
#include <cuda_runtime.h>
#include <math.h>
#include <float.h>

#define TT 5
#define CC 3
#define HH 384
#define WW 384
#define KK 10
#define NHH 96
#define NWW 96
#define NQ (TT*NHH*NWW)      /* 46080 */
#define WPB 4                /* warps (queries) per block */
#define RSTR 18              /* region row stride in floats (8B-aligned rows, conflict pad) */
#define QSTR 8               /* query row stride */

typedef unsigned long long u64;

__device__ double       g_accum;  /* zero-init at load; self-reset each run */
__device__ unsigned int g_count;

__device__ __forceinline__ void upk2(u64 v, float& lo, float& hi) {
    asm("mov.b64 {%0, %1}, %2;" : "=f"(lo), "=f"(hi) : "l"(v));
}
__device__ __forceinline__ void fma2(u64& d, u64 a, u64 b) {
    asm("fma.rn.f32x2 %0, %1, %2, %0;" : "+l"(d) : "l"(a), "l"(b));
}

__global__ void __launch_bounds__(32*WPB)
fused_kernel(const float* __restrict__ vid,
             const float* __restrict__ fflow,
             const float* __restrict__ bflow,
             float* __restrict__ out, int out_size)
{
    __shared__ __align__(16) float s_region[WPB][3*3*15*RSTR];  /* 9720B/warp */
    __shared__ __align__(16) float s_qR[WPB][3*7*QSTR];         /* {q0..q6,0}  */
    __shared__ __align__(16) float s_qL[WPB][3*7*QSTR];         /* {0,q0..q6}  */
    __shared__ int   s_meta[WPB][16];

    const int warp = threadIdx.x >> 5;
    const int lane = threadIdx.x & 31;
    const int qidx = blockIdx.x * WPB + warp;

    const int ti = qidx / (NHH * NWW);
    const int rr = qidx - ti * (NHH * NWW);
    const int hi = (rr / NWW) * 4;
    const int wi = (rr % NWW) * 4;

    float* region = s_region[warp];
    float* qR     = s_qR[warp];
    float* qL     = s_qL[warp];
    int*   meta   = s_meta[warp];

    /* ---- meta per temporal offset di (0: t-1/bflow, 1: t/zero, 2: t+1/fflow) ---- */
    if (lane < 3) {
        int di = lane;
        int tj, bh, bw;
        if (di == 1) { tj = ti; bh = hi; bw = wi; }
        else {
            const float* fl = (di == 0) ? bflow : fflow;
            tj = (di == 0) ? max(ti - 1, 0) : min(ti + 1, TT - 1);
            float fx = fl[((ti*2 + 0)*HH + hi)*WW + wi];
            float fy = fl[((ti*2 + 1)*HH + hi)*WW + wi];
            bh = min(max(hi + (int)rintf(fy), 0), HH - 1);
            bw = min(max(wi + (int)rintf(fx), 0), WW - 1);
        }
        meta[di*5 + 0] = tj;
        meta[di*5 + 1] = max(bh - 4, 0);   /* ystart */
        meta[di*5 + 2] = max(bw - 4, 0);   /* xstart */
        meta[di*5 + 3] = bh;
        meta[di*5 + 4] = bw;
    }

    /* ---- query patch: right-padded + left-padded copies; partial Sum(q^2) ---- */
    float qsq_part = 0.f;
    for (int e = lane; e < 3*7*QSTR; e += 32) {
        int row = e >> 3;          /* c*7+py */
        int px  = e & 7;
        float val = 0.f;
        if (px < 7) {
            int c  = row / 7, py = row - (row/7)*7;
            int y = min(hi + py, HH - 1);
            int x = min(wi + px, WW - 1);
            val = vid[((ti*CC + c)*HH + y)*WW + x];
            qsq_part = fmaf(val, val, qsq_part);
        }
        qR[e] = val;
        qL[(row << 3) + ((px + 1) & 7)] = val;   /* px==7 -> slot 0 gets 0 */
    }
    #pragma unroll
    for (int off = 16; off; off >>= 1)
        qsq_part += __shfl_xor_sync(0xffffffffu, qsq_part, off);
    const float qs = qsq_part;
    __syncwarp();

    /* ---- 3 regions of 15 rows x 16 cols x 3c (row/col saturated) ---- */
    for (int e = lane; e < 3*3*15*16; e += 32) {
        int di = e / 720; int r1 = e - di*720;
        int c  = r1 / 240; int r2 = r1 - c*240;
        int ry = r2 >> 4;  int rx = r2 & 15;
        int tj = meta[di*5 + 0];
        int y  = min(meta[di*5 + 1] + ry, HH - 1);
        int x  = min(meta[di*5 + 2] + rx, WW - 1);
        region[((di*3 + c)*15 + ry)*RSTR + rx] =
            vid[((tj*CC + c)*HH + y)*WW + x];
    }
    __syncwarp();

    float d[9];
    #pragma unroll
    for (int j = 0; j < 9; j++) d[j] = FLT_MAX;

    if (lane < 27) {
        int di = lane / 9, sy = lane - di*9;
        int ys = meta[di*5 + 1], xs = meta[di*5 + 2];
        int bh = meta[di*5 + 3], bw = meta[di*5 + 4];
        int rowoff = min(max(bh - 4 + sy, 0), HH - 1) - ys;
        const float* regdi = region + di*3*15*RSTR;
        bool fastx = (bw >= 4) && (bw <= WW - 11);

        if (fastx) {
            u64 acc[9], sq2[8];
            #pragma unroll
            for (int s = 0; s < 9; s++) acc[s] = 0ull;
            #pragma unroll
            for (int p = 0; p < 8; p++) sq2[p] = 0ull;

            #pragma unroll
            for (int c = 0; c < 3; c++) {
                #pragma unroll
                for (int py = 0; py < 7; py++) {
                    const u64* vrow = (const u64*)(regdi + (c*15 + rowoff + py)*RSTR);
                    const u64* qr   = (const u64*)(qR + (c*7 + py)*QSTR);
                    const u64* ql   = (const u64*)(qL + (c*7 + py)*QSTR);
                    u64 ve[8];
                    #pragma unroll
                    for (int p = 0; p < 8; p++) ve[p] = vrow[p];
                    u64 qe[4], qo[4];
                    #pragma unroll
                    for (int j = 0; j < 4; j++) { qe[j] = qr[j]; qo[j] = ql[j]; }

                    #pragma unroll
                    for (int j = 0; j < 4; j++) {
                        #pragma unroll
                        for (int e2 = 0; e2 < 5; e2++)      /* sx = 0,2,4,6,8 */
                            fma2(acc[2*e2], qe[j], ve[e2 + j]);
                        #pragma unroll
                        for (int o = 0; o < 4; o++)         /* sx = 1,3,5,7 */
                            fma2(acc[2*o + 1], qo[j], ve[o + j]);
                    }
                    #pragma unroll
                    for (int p = 0; p < 8; p++) fma2(sq2[p], ve[p], ve[p]);
                }
            }

            /* epilogue: prefix-sum sliding window for Sum(v^2) */
            float col[15];
            {
                float lo, hiv;
                #pragma unroll
                for (int p = 0; p < 7; p++) { upk2(sq2[p], lo, hiv); col[2*p] = lo; col[2*p+1] = hiv; }
                upk2(sq2[7], lo, hiv); col[14] = lo;
            }
            float pre[16]; pre[0] = 0.f;
            #pragma unroll
            for (int j = 0; j < 15; j++) pre[j+1] = pre[j] + col[j];
            #pragma unroll
            for (int sx = 0; sx < 9; sx++) {
                float alo, ahi; upk2(acc[sx], alo, ahi);
                float qv = alo + ahi;
                float vs = pre[sx+7] - pre[sx];
                d[sx] = fmaf(-2.f, qv, qs + vs);
            }
        } else {
            /* rare x-border path: direct scalar SSD with per-sx clamped col offset */
            #pragma unroll
            for (int sx = 0; sx < 9; sx++) {
                int co = min(max(bw - 4 + sx, 0), WW - 1) - xs;
                float a = 0.f;
                for (int c = 0; c < 3; c++) {
                    for (int py = 0; py < 7; py++) {
                        const float* row = regdi + (c*15 + rowoff + py)*RSTR + co;
                        const float* qrow = qR + (c*7 + py)*QSTR;
                        #pragma unroll
                        for (int px = 0; px < 7; px++) {
                            float t = qrow[px] - row[px];
                            a = fmaf(t, t, a);
                        }
                    }
                }
                d[sx] = a;
            }
        }
    }

    /* ---- register-resident top-10 (tie-aware extract-min) ---- */
    float sumK = 0.f;
    int need = KK;
    while (need > 0) {
        float m = d[0];
        #pragma unroll
        for (int j = 1; j < 9; j++) m = fminf(m, d[j]);
        #pragma unroll
        for (int off = 16; off; off >>= 1)
            m = fminf(m, __shfl_xor_sync(0xffffffffu, m, off));
        unsigned cnt = 0;
        #pragma unroll
        for (int j = 0; j < 9; j++)
            if (d[j] == m) { d[j] = FLT_MAX; cnt++; }
        unsigned tot = __reduce_add_sync(0xffffffffu, cnt);
        int take = min((int)tot, need);
        sumK += m * (float)take;
        need -= take;
    }
    if (lane == 0) atomicAdd(&g_accum, (double)sumK);

    /* ---- last-block finalize + reset (single-launch, graph-safe) ---- */
    __threadfence();
    __syncthreads();
    if (threadIdx.x == 0) {
        unsigned prev = atomicAdd(&g_count, 1u);
        if (prev == gridDim.x - 1) {
            double s = atomicAdd(&g_accum, 0.0);
            float mean = (float)(s / ((double)NQ * (double)KK));
            for (int i = 0; i < out_size; i++) out[i] = mean;
            g_count = 0u;
            g_accum = 0.0;
            __threadfence();
        }
    }
}

extern "C" void kernel_launch(void* const* d_in, const int* in_sizes, int n_in,
                              void* d_out, int out_size) {
    const float* noisy = (const float*)d_in[0];
    /* d_in[1] = deno: dead (SEARCH_INPUT='noisy', refine reads noisy) */
    const float* fflow = (const float*)d_in[2];
    const float* bflow = (const float*)d_in[3];
    float* out = (float*)d_out;

    fused_kernel<<<NQ / WPB, 32 * WPB>>>(noisy, fflow, bflow, out, out_size);
}

// round 4
// speedup vs baseline: 1.3969x; 1.2687x over previous
#include <cuda_runtime.h>
#include <math.h>
#include <float.h>

#define TT 5
#define CC 3
#define HH 384
#define WW 384
#define KK 10
#define NHH 96
#define NWW 96
#define NQ (TT*NHH*NWW)      /* 46080 */
#define WPB 4                /* warps (queries) per block */
#define RSTR 18              /* region row stride in floats */
#define QSTR 8               /* query row stride */

typedef unsigned long long u64;

__device__ double       g_accum;  /* zero-init at load; self-reset each run */
__device__ unsigned int g_count;

__device__ __forceinline__ void upk2(u64 v, float& lo, float& hi) {
    asm("mov.b64 {%0, %1}, %2;" : "=f"(lo), "=f"(hi) : "l"(v));
}
__device__ __forceinline__ void fma2(u64& d, u64 a, u64 b) {
    asm("fma.rn.f32x2 %0, %1, %2, %0;" : "+l"(d) : "l"(a), "l"(b));
}

__global__ void __launch_bounds__(32*WPB, 5)
fused_kernel(const float* __restrict__ vid,
             const float* __restrict__ fflow,
             const float* __restrict__ bflow,
             float* __restrict__ out, int out_size)
{
    __shared__ __align__(16) float s_region[WPB][3*3*15*RSTR];  /* 9720B/warp */
    __shared__ __align__(16) float s_qR[WPB][3*7*QSTR];         /* {q0..q6,0}  */
    __shared__ __align__(16) float s_qL[WPB][3*7*QSTR];         /* {0,q0..q6}  */
    __shared__ int   s_meta[WPB][16];

    const int warp = threadIdx.x >> 5;
    const int lane = threadIdx.x & 31;
    const int qidx = blockIdx.x * WPB + warp;

    const int ti = qidx / (NHH * NWW);
    const int rr = qidx - ti * (NHH * NWW);
    const int hi = (rr / NWW) * 4;
    const int wi = (rr % NWW) * 4;

    float* region = s_region[warp];
    float* qR     = s_qR[warp];
    float* qL     = s_qL[warp];
    int*   meta   = s_meta[warp];

    /* ---- meta per temporal offset di (0: t-1/bflow, 1: t/zero, 2: t+1/fflow) ---- */
    if (lane < 3) {
        int di = lane;
        int tj, bh, bw;
        if (di == 1) { tj = ti; bh = hi; bw = wi; }
        else {
            const float* fl = (di == 0) ? bflow : fflow;
            tj = (di == 0) ? max(ti - 1, 0) : min(ti + 1, TT - 1);
            float fx = fl[((ti*2 + 0)*HH + hi)*WW + wi];
            float fy = fl[((ti*2 + 1)*HH + hi)*WW + wi];
            bh = min(max(hi + (int)rintf(fy), 0), HH - 1);
            bw = min(max(wi + (int)rintf(fx), 0), WW - 1);
        }
        meta[di*5 + 0] = tj;
        meta[di*5 + 1] = max(bh - 4, 0);   /* ystart */
        meta[di*5 + 2] = max(bw - 4, 0);   /* xstart */
        meta[di*5 + 3] = bh;
        meta[di*5 + 4] = bw;
    }

    /* ---- query patch: right-padded + left-padded copies; Sum(q^2) ---- */
    float qsq_part = 0.f;
    for (int e = lane; e < 3*7*QSTR; e += 32) {
        int row = e >> 3;          /* c*7+py */
        int px  = e & 7;
        float val = 0.f;
        if (px < 7) {
            int c  = row / 7, py = row - (row/7)*7;
            int y = min(hi + py, HH - 1);
            int x = min(wi + px, WW - 1);
            val = vid[((ti*CC + c)*HH + y)*WW + x];
            qsq_part = fmaf(val, val, qsq_part);
        }
        qR[e] = val;
        qL[(row << 3) + ((px + 1) & 7)] = val;   /* px==7 -> slot 0 gets 0 */
    }
    #pragma unroll
    for (int off = 16; off; off >>= 1)
        qsq_part += __shfl_xor_sync(0xffffffffu, qsq_part, off);
    const float qs = qsq_part;
    __syncwarp();

    /* ---- region load: 9 (di,c) groups of 15 rows x 16 cols, hoisted math ---- */
    #pragma unroll
    for (int di = 0; di < 3; di++) {
        const int tj = meta[di*5 + 0];
        const int ys = meta[di*5 + 1];
        const int xs = meta[di*5 + 2];
        const bool safe = (ys <= HH - 15) && (xs <= WW - 16);
        #pragma unroll
        for (int c = 0; c < 3; c++) {
            const float* src = vid + (tj*CC + c)*(HH*WW);
            float* dst = region + (di*3 + c)*15*RSTR;
            if (safe) {
                const float* s2 = src + ys*WW + xs;
                #pragma unroll 4
                for (int i = lane; i < 240; i += 32) {
                    int ry = i >> 4, rx = i & 15;
                    dst[ry*RSTR + rx] = __ldg(s2 + ry*WW + rx);
                }
            } else {
                #pragma unroll 4
                for (int i = lane; i < 240; i += 32) {
                    int ry = i >> 4, rx = i & 15;
                    int y = min(ys + ry, HH - 1);
                    int x = min(xs + rx, WW - 1);
                    dst[ry*RSTR + rx] = __ldg(src + y*WW + x);
                }
            }
        }
    }
    __syncwarp();

    float d[9];
    #pragma unroll
    for (int j = 0; j < 9; j++) d[j] = FLT_MAX;

    if (lane < 27) {
        int di = lane / 9, sy = lane - di*9;
        int ys = meta[di*5 + 1], xs = meta[di*5 + 2];
        int bh = meta[di*5 + 3], bw = meta[di*5 + 4];
        int rowoff = min(max(bh - 4 + sy, 0), HH - 1) - ys;
        const float* regdi = region + di*3*15*RSTR;
        bool fastx = (bw >= 4) && (bw <= WW - 11);

        if (fastx) {
            u64 acc[9], sq2[8];
            #pragma unroll
            for (int s = 0; s < 9; s++) acc[s] = 0ull;
            #pragma unroll
            for (int p = 0; p < 8; p++) sq2[p] = 0ull;

            #pragma unroll
            for (int c = 0; c < 3; c++) {
                #pragma unroll
                for (int py = 0; py < 7; py++) {
                    const u64* vrow = (const u64*)(regdi + (c*15 + rowoff + py)*RSTR);
                    const u64* qr   = (const u64*)(qR + (c*7 + py)*QSTR);
                    const u64* ql   = (const u64*)(qL + (c*7 + py)*QSTR);
                    u64 ve[8];
                    #pragma unroll
                    for (int p = 0; p < 8; p++) ve[p] = vrow[p];
                    u64 qe[4], qo[4];
                    #pragma unroll
                    for (int j = 0; j < 4; j++) { qe[j] = qr[j]; qo[j] = ql[j]; }

                    #pragma unroll
                    for (int j = 0; j < 4; j++) {
                        #pragma unroll
                        for (int e2 = 0; e2 < 5; e2++)      /* sx = 0,2,4,6,8 */
                            fma2(acc[2*e2], qe[j], ve[e2 + j]);
                        #pragma unroll
                        for (int o = 0; o < 4; o++)         /* sx = 1,3,5,7 */
                            fma2(acc[2*o + 1], qo[j], ve[o + j]);
                    }
                    #pragma unroll
                    for (int p = 0; p < 8; p++) fma2(sq2[p], ve[p], ve[p]);
                }
            }

            /* epilogue: prefix-sum sliding window for Sum(v^2) */
            float col[15];
            {
                float lo, hiv;
                #pragma unroll
                for (int p = 0; p < 7; p++) { upk2(sq2[p], lo, hiv); col[2*p] = lo; col[2*p+1] = hiv; }
                upk2(sq2[7], lo, hiv); col[14] = lo;
            }
            float pre[16]; pre[0] = 0.f;
            #pragma unroll
            for (int j = 0; j < 15; j++) pre[j+1] = pre[j] + col[j];
            #pragma unroll
            for (int sx = 0; sx < 9; sx++) {
                float alo, ahi; upk2(acc[sx], alo, ahi);
                float qv = alo + ahi;
                float vs = pre[sx+7] - pre[sx];
                d[sx] = fmaf(-2.f, qv, qs + vs);
            }
        } else {
            /* rare x-border path: direct scalar SSD with per-sx clamped col offset */
            #pragma unroll
            for (int sx = 0; sx < 9; sx++) {
                int co = min(max(bw - 4 + sx, 0), WW - 1) - xs;
                float a = 0.f;
                for (int c = 0; c < 3; c++) {
                    for (int py = 0; py < 7; py++) {
                        const float* row = regdi + (c*15 + rowoff + py)*RSTR + co;
                        const float* qrow = qR + (c*7 + py)*QSTR;
                        #pragma unroll
                        for (int px = 0; px < 7; px++) {
                            float t = qrow[px] - row[px];
                            a = fmaf(t, t, a);
                        }
                    }
                }
                d[sx] = a;
            }
        }
    }

    /* ---- top-10 via REDUX.MIN on monotone uint keys (clamped >= 0) ---- */
    unsigned k[9];
    #pragma unroll
    for (int j = 0; j < 9; j++) k[j] = __float_as_uint(fmaxf(d[j], 0.f));

    float sumK = 0.f;
    unsigned need = KK;
    #pragma unroll 1
    while (need) {
        unsigned mloc = k[0];
        #pragma unroll
        for (int j = 1; j < 9; j++) mloc = min(mloc, k[j]);
        unsigned m = __reduce_min_sync(0xffffffffu, mloc);
        unsigned cl = 0;
        #pragma unroll
        for (int j = 0; j < 9; j++) {
            if (k[j] == m) { k[j] = 0xffffffffu; cl++; }
        }
        unsigned tot = __reduce_add_sync(0xffffffffu, cl);
        unsigned take = min(tot, need);
        sumK += __uint_as_float(m) * (float)take;
        need -= take;
    }
    if (lane == 0) atomicAdd(&g_accum, (double)sumK);

    /* ---- last-block finalize + reset (single-launch, graph-safe) ---- */
    __threadfence();
    __syncthreads();
    if (threadIdx.x == 0) {
        unsigned prev = atomicAdd(&g_count, 1u);
        if (prev == gridDim.x - 1) {
            double s = atomicAdd(&g_accum, 0.0);
            float mean = (float)(s / ((double)NQ * (double)KK));
            for (int i = 0; i < out_size; i++) out[i] = mean;
            g_count = 0u;
            g_accum = 0.0;
            __threadfence();
        }
    }
}

extern "C" void kernel_launch(void* const* d_in, const int* in_sizes, int n_in,
                              void* d_out, int out_size) {
    const float* noisy = (const float*)d_in[0];
    /* d_in[1] = deno: dead (SEARCH_INPUT='noisy', refine reads noisy) */
    const float* fflow = (const float*)d_in[2];
    const float* bflow = (const float*)d_in[3];
    float* out = (float*)d_out;

    fused_kernel<<<NQ / WPB, 32 * WPB>>>(noisy, fflow, bflow, out, out_size);
}

// round 5
// speedup vs baseline: 2.0317x; 1.4544x over previous
#include <cuda_runtime.h>
#include <math.h>
#include <float.h>

#define TT 5
#define CC 3
#define HH 384
#define WW 384
#define HW (HH*WW)
#define KK 10
#define NHH 96
#define NWW 96
#define NQ (TT*NHH*NWW)      /* 46080 */
#define WPB 4                /* warps (queries) per block */
#define RSTR 18              /* private region row stride (floats) */
#define SSTR 30              /* shared di=1 region row stride (floats) */
#define QSTR 8

typedef unsigned long long u64;

__device__ double       g_accum;
__device__ unsigned int g_count;

__device__ __forceinline__ void upk2(u64 v, float& lo, float& hi) {
    asm("mov.b64 {%0, %1}, %2;" : "=f"(lo), "=f"(hi) : "l"(v));
}
__device__ __forceinline__ void fma2(u64& d, u64 a, u64 b) {
    asm("fma.rn.f32x2 %0, %1, %2, %0;" : "+l"(d) : "l"(a), "l"(b));
}

__global__ void __launch_bounds__(32*WPB, 6)
fused_kernel(const float* __restrict__ vid,
             const float* __restrict__ fflow,
             const float* __restrict__ bflow,
             float* __restrict__ out, int out_size)
{
    /* per-warp: di=0 and di=2 regions (2 x 3c x 15 x 18) */
    __shared__ __align__(16) float s_region[WPB][2*3*15*RSTR];   /* 25920B */
    /* block-shared di=1 region: 3c x 15 rows x 28 cols (stride 30) */
    __shared__ __align__(16) float s_sh[3*15*SSTR];              /* 5400B  */
    __shared__ __align__(16) float s_qR[WPB][3*7*QSTR];
    __shared__ __align__(16) float s_qL[WPB][3*7*QSTR];
    __shared__ int   s_meta[WPB][12];   /* per di: tj, ys, bh, bw */

    const int tid  = threadIdx.x;
    const int warp = tid >> 5;
    const int lane = tid & 31;
    const int qidx = blockIdx.x * WPB + warp;

    const int ti = qidx / (NHH * NWW);
    const int rr = qidx - ti * (NHH * NWW);
    const int hi = (rr / NWW) * 4;
    const int wi = (rr % NWW) * 4;
    const int wi0 = wi - 4*warp;         /* block's first-warp wi (same ti,hi) */

    float* region = s_region[warp];
    float* qR     = s_qR[warp];
    float* qL     = s_qL[warp];
    int*   meta   = s_meta[warp];

    /* ---- meta per di (0: t-1/bflow, 1: t/zero, 2: t+1/fflow) ---- */
    if (lane < 3) {
        int di = lane;
        int tj, bh, bw;
        if (di == 1) { tj = ti; bh = hi; bw = wi; }
        else {
            const float* fl = (di == 0) ? bflow : fflow;
            tj = (di == 0) ? max(ti - 1, 0) : min(ti + 1, TT - 1);
            float fx = fl[((ti*2 + 0)*HH + hi)*WW + wi];
            float fy = fl[((ti*2 + 1)*HH + hi)*WW + wi];
            bh = min(max(hi + (int)rintf(fy), 0), HH - 1);
            bw = min(max(wi + (int)rintf(fx), 0), WW - 1);
        }
        meta[di*4 + 0] = tj;
        meta[di*4 + 1] = max(bh - 4, 0);
        meta[di*4 + 2] = bh;
        meta[di*4 + 3] = bw;
    }

    /* ---- query patch: right/left padded copies; Sum(q^2) ---- */
    float qsq_part = 0.f;
    #pragma unroll
    for (int k = 0; k < 6; k++) {
        int e = lane + 32*k;
        if (e < 168) {
            int row = e >> 3, px = e & 7;
            float val = 0.f;
            if (px < 7) {
                int c = row / 7, py = row - c*7;
                int y = min(hi + py, HH - 1);
                int x = min(wi + px, WW - 1);
                val = vid[((ti*CC + c)*HH + y)*WW + x];
                qsq_part = fmaf(val, val, qsq_part);
            }
            qR[e] = val;
            qL[(row << 3) + ((px + 1) & 7)] = val;
        }
    }
    #pragma unroll
    for (int off = 16; off; off >>= 1)
        qsq_part += __shfl_xor_sync(0xffffffffu, qsq_part, off);
    const float qs = qsq_part;
    __syncwarp();

    /* ---- per-warp regions for di=0 and di=2 ---- */
    {
        const int ry = lane >> 4, rx = lane & 15;
        #pragma unroll
        for (int ds = 0; ds < 2; ds++) {
            const int di = ds*2;
            const int tj = meta[di*4 + 0];
            const int ys = meta[di*4 + 1];
            const int bw = meta[di*4 + 3];
            const int xs = max(bw - 4, 0);
            float* dst0 = region + ds*(3*15*RSTR) + ry*RSTR + rx;
            if (ys <= HH-15 && xs <= WW-16) {
                const float* src0 = vid + tj*3*HW + (ys + ry)*WW + xs + rx;
                #pragma unroll
                for (int c = 0; c < 3; c++) {
                    const float* s2 = src0 + c*HW;
                    float* d2 = dst0 + c*(15*RSTR);
                    #pragma unroll
                    for (int k = 0; k < 8; k++) {
                        if (ry + 2*k < 15) d2[k*2*RSTR] = s2[k*2*WW];
                    }
                }
            } else {
                const float* src = vid + tj*3*HW;
                #pragma unroll
                for (int c = 0; c < 3; c++) {
                    #pragma unroll
                    for (int k = 0; k < 8; k++) {
                        int r = ry + 2*k;
                        if (r < 15) {
                            int y = min(ys + r, HH-1);
                            int x = min(xs + rx, WW-1);
                            dst0[c*(15*RSTR) + (r - ry)*RSTR + 0] = 0.f; /* placeholder avoided below */
                            region[ds*(3*15*RSTR) + (c*15 + r)*RSTR + rx] = src[c*HW + y*WW + x];
                        }
                    }
                }
            }
        }
    }

    /* ---- block-shared di=1 region: 3c x 15 x 28 cols ---- */
    {
        const int rx = tid & 31, r0 = tid >> 5;   /* r0 in 0..3 */
        const int ysS = max(hi - 4, 0);
        const int xsS = max(wi0 - 4, 0);
        if (rx < 28) {
            if (ysS <= HH-15 && xsS <= WW-28) {
                const float* src = vid + ti*3*HW + (ysS + r0)*WW + xsS + rx;
                float* dst = s_sh + r0*SSTR + rx;
                #pragma unroll
                for (int c = 0; c < 3; c++) {
                    #pragma unroll
                    for (int k = 0; k < 4; k++) {
                        if (r0 + 4*k < 15) dst[c*(15*SSTR) + k*4*SSTR] = src[c*HW + k*4*WW];
                    }
                }
            } else {
                #pragma unroll
                for (int c = 0; c < 3; c++) {
                    #pragma unroll
                    for (int k = 0; k < 4; k++) {
                        int r = r0 + 4*k;
                        if (r < 15) {
                            int y = min(ysS + r, HH-1);
                            int x = min(xsS + rx, WW-1);
                            s_sh[(c*15 + r)*SSTR + rx] = vid[(ti*3 + c)*HW + y*WW + x];
                        }
                    }
                }
            }
        }
    }
    __syncthreads();

    float d[9];
    #pragma unroll
    for (int j = 0; j < 9; j++) d[j] = FLT_MAX;

    if (lane < 27) {
        const int di = lane / 9, sy = lane - di*9;
        const int ys = meta[di*4 + 1];
        const int bh = meta[di*4 + 2];
        const int bw = meta[di*4 + 3];
        const int rowoff = min(max(bh - 4 + sy, 0), HH - 1) - ys;
        const int xsS = max(wi0 - 4, 0);
        const int xb  = (di == 1) ? xsS : max(bw - 4, 0);   /* region col-0 origin */
        const int stride = (di == 1) ? SSTR : RSTR;
        const float* base = (di == 1) ? s_sh
                                      : region + (di == 0 ? 0 : 3*15*RSTR);
        const int xoff = max(bw - 4, 0) - xb;               /* 0 for private */
        const bool fastx = (bw >= 4) && (bw <= WW - 11);

        if (fastx) {
            u64 acc[9], sq2[8];
            #pragma unroll
            for (int s = 0; s < 9; s++) acc[s] = 0ull;
            #pragma unroll
            for (int p = 0; p < 8; p++) sq2[p] = 0ull;

            const float* pb = base + rowoff*stride + xoff;
            #pragma unroll
            for (int c = 0; c < 3; c++) {
                #pragma unroll
                for (int py = 0; py < 7; py++) {
                    const u64* vrow = (const u64*)(pb + (c*15 + py)*stride);
                    const u64* qr   = (const u64*)(qR + (c*7 + py)*QSTR);
                    const u64* ql   = (const u64*)(qL + (c*7 + py)*QSTR);
                    u64 ve[8];
                    #pragma unroll
                    for (int p = 0; p < 8; p++) ve[p] = vrow[p];

                    #pragma unroll
                    for (int j = 0; j < 4; j++) {
                        u64 qe = qr[j], qo = ql[j];
                        #pragma unroll
                        for (int e2 = 0; e2 < 5; e2++)      /* sx = 0,2,4,6,8 */
                            fma2(acc[2*e2], qe, ve[e2 + j]);
                        #pragma unroll
                        for (int o = 0; o < 4; o++)         /* sx = 1,3,5,7 */
                            fma2(acc[2*o + 1], qo, ve[o + j]);
                    }
                    #pragma unroll
                    for (int p = 0; p < 8; p++) fma2(sq2[p], ve[p], ve[p]);
                }
            }

            float col[15];
            {
                float lo, hiv;
                #pragma unroll
                for (int p = 0; p < 7; p++) { upk2(sq2[p], lo, hiv); col[2*p] = lo; col[2*p+1] = hiv; }
                upk2(sq2[7], lo, hiv); col[14] = lo;
            }
            float pre[16]; pre[0] = 0.f;
            #pragma unroll
            for (int j = 0; j < 15; j++) pre[j+1] = pre[j] + col[j];
            #pragma unroll
            for (int sx = 0; sx < 9; sx++) {
                float alo, ahi; upk2(acc[sx], alo, ahi);
                float qv = alo + ahi;
                float vs = pre[sx+7] - pre[sx];
                d[sx] = fmaf(-2.f, qv, qs + vs);
            }
        } else {
            /* rare x-border path: scalar SSD, cols clamped relative to region origin xb */
            #pragma unroll
            for (int sx = 0; sx < 9; sx++) {
                int co = min(max(bw - 4 + sx, 0), WW - 1) - xb;
                float a = 0.f;
                for (int c = 0; c < 3; c++) {
                    for (int py = 0; py < 7; py++) {
                        const float* row = base + (c*15 + rowoff + py)*stride + co;
                        const float* qrow = qR + (c*7 + py)*QSTR;
                        #pragma unroll
                        for (int px = 0; px < 7; px++) {
                            float t = qrow[px] - row[px];
                            a = fmaf(t, t, a);
                        }
                    }
                }
                d[sx] = a;
            }
        }
    }

    /* ---- top-10 via REDUX.MIN on monotone uint keys ---- */
    unsigned k[9];
    #pragma unroll
    for (int j = 0; j < 9; j++) k[j] = __float_as_uint(fmaxf(d[j], 0.f));

    float sumK = 0.f;
    unsigned need = KK;
    #pragma unroll 1
    while (need) {
        unsigned mloc = k[0];
        #pragma unroll
        for (int j = 1; j < 9; j++) mloc = min(mloc, k[j]);
        unsigned m = __reduce_min_sync(0xffffffffu, mloc);
        unsigned cl = 0;
        #pragma unroll
        for (int j = 0; j < 9; j++) {
            if (k[j] == m) { k[j] = 0xffffffffu; cl++; }
        }
        unsigned tot = __reduce_add_sync(0xffffffffu, cl);
        unsigned take = min(tot, need);
        sumK += __uint_as_float(m) * (float)take;
        need -= take;
    }
    if (lane == 0) atomicAdd(&g_accum, (double)sumK);

    /* ---- last-block finalize + reset ---- */
    __threadfence();
    __syncthreads();
    if (tid == 0) {
        unsigned prev = atomicAdd(&g_count, 1u);
        if (prev == gridDim.x - 1) {
            double s = atomicAdd(&g_accum, 0.0);
            float mean = (float)(s / ((double)NQ * (double)KK));
            for (int i = 0; i < out_size; i++) out[i] = mean;
            g_count = 0u;
            g_accum = 0.0;
            __threadfence();
        }
    }
}

extern "C" void kernel_launch(void* const* d_in, const int* in_sizes, int n_in,
                              void* d_out, int out_size) {
    const float* noisy = (const float*)d_in[0];
    /* d_in[1] = deno: dead */
    const float* fflow = (const float*)d_in[2];
    const float* bflow = (const float*)d_in[3];
    float* out = (float*)d_out;

    fused_kernel<<<NQ / WPB, 32 * WPB>>>(noisy, fflow, bflow, out, out_size);
}

// round 6
// speedup vs baseline: 2.0351x; 1.0017x over previous
#include <cuda_runtime.h>
#include <math.h>
#include <float.h>

#define TT 5
#define CC 3
#define HH 384
#define WW 384
#define HW (HH*WW)
#define KK 10
#define NHH 96
#define NWW 96
#define NQ (TT*NHH*NWW)      /* 46080 */
#define WPB 4                /* warps (queries) per block */
#define RSTR 18              /* private region row stride (conflict-free: 18r mod 32 distinct) */
#define SSTR 30              /* shared di=1 region row stride */
#define QSTR 8

typedef unsigned long long u64;

__device__ double       g_accum;
__device__ unsigned int g_count;

__device__ __forceinline__ void upk2(u64 v, float& lo, float& hi) {
    asm("mov.b64 {%0, %1}, %2;" : "=f"(lo), "=f"(hi) : "l"(v));
}
__device__ __forceinline__ void fma2(u64& d, u64 a, u64 b) {
    asm("fma.rn.f32x2 %0, %1, %2, %0;" : "+l"(d) : "l"(a), "l"(b));
}

__global__ void __launch_bounds__(32*WPB, 6)
fused_kernel(const float* __restrict__ vid,
             const float* __restrict__ fflow,
             const float* __restrict__ bflow,
             float* __restrict__ out, int out_size)
{
    __shared__ __align__(16) float s_region[WPB][2*3*15*RSTR];   /* di=0,2: 25920B */
    __shared__ __align__(16) float s_sh[3*15*SSTR];              /* di=1 block-shared: 5400B */
    __shared__ __align__(16) float s_qR[WPB][3*7*QSTR];          /* {q0..q6,0} */
    __shared__ __align__(16) float s_qL[WPB][3*7*QSTR];          /* {0,q0..q6} */
    __shared__ int   s_meta[WPB][12];                            /* per di: tj, ys, bh, bw */

    const int tid  = threadIdx.x;
    const int warp = tid >> 5;
    const int lane = tid & 31;
    const int qidx = blockIdx.x * WPB + warp;

    const int ti = qidx / (NHH * NWW);
    const int rr = qidx - ti * (NHH * NWW);
    const int hi = (rr / NWW) * 4;
    const int wi = (rr % NWW) * 4;
    const int wi0 = wi - 4*warp;          /* block's first-warp wi (same ti,hi) */

    float* region = s_region[warp];
    float* qR     = s_qR[warp];
    float* qL     = s_qL[warp];
    int*   meta   = s_meta[warp];

    /* ---- meta per di (0: t-1/bflow, 1: t/zero, 2: t+1/fflow) ---- */
    if (lane < 3) {
        int di = lane;
        int tj, bh, bw;
        if (di == 1) { tj = ti; bh = hi; bw = wi; }
        else {
            const float* fl = (di == 0) ? bflow : fflow;
            tj = (di == 0) ? max(ti - 1, 0) : min(ti + 1, TT - 1);
            float fx = fl[((ti*2 + 0)*HH + hi)*WW + wi];
            float fy = fl[((ti*2 + 1)*HH + hi)*WW + wi];
            bh = min(max(hi + (int)rintf(fy), 0), HH - 1);
            bw = min(max(wi + (int)rintf(fx), 0), WW - 1);
        }
        meta[di*4 + 0] = tj;
        meta[di*4 + 1] = max(bh - 4, 0);
        meta[di*4 + 2] = bh;
        meta[di*4 + 3] = bw;
    }
    __syncwarp();

    /* ---- block-shared di=1 region: 3c x 15 rows x 28 cols ---- */
    {
        const int rx = tid & 31, r0 = tid >> 5;   /* r0 in 0..3 */
        const int ysS = max(hi - 4, 0);
        const int xsS = max(wi0 - 4, 0);
        if (rx < 28) {
            if (ysS <= HH-15 && xsS <= WW-28) {
                const float* src = vid + ti*3*HW + (ysS + r0)*WW + xsS + rx;
                float* dst = s_sh + r0*SSTR + rx;
                #pragma unroll
                for (int c = 0; c < 3; c++) {
                    #pragma unroll
                    for (int k = 0; k < 4; k++) {
                        if (r0 + 4*k < 15) dst[c*(15*SSTR) + k*4*SSTR] = src[c*HW + k*4*WW];
                    }
                }
            } else {
                #pragma unroll
                for (int c = 0; c < 3; c++) {
                    #pragma unroll
                    for (int k = 0; k < 4; k++) {
                        int r = r0 + 4*k;
                        if (r < 15) {
                            int y = min(ysS + r, HH-1);
                            int x = min(xsS + rx, WW-1);
                            s_sh[(c*15 + r)*SSTR + rx] = vid[(ti*3 + c)*HW + y*WW + x];
                        }
                    }
                }
            }
        }
    }

    /* ---- per-warp regions for di=0 and di=2 ---- */
    {
        const int ry = lane >> 4, rx = lane & 15;
        #pragma unroll
        for (int ds = 0; ds < 2; ds++) {
            const int di = ds*2;
            const int tj = meta[di*4 + 0];
            const int ys = meta[di*4 + 1];
            const int bw = meta[di*4 + 3];
            const int xs = max(bw - 4, 0);
            if (ys <= HH-15 && xs <= WW-16) {
                const float* src0 = vid + tj*3*HW + (ys + ry)*WW + xs + rx;
                float* dst0 = region + ds*(3*15*RSTR) + ry*RSTR + rx;
                #pragma unroll
                for (int c = 0; c < 3; c++) {
                    const float* s2 = src0 + c*HW;
                    float* d2 = dst0 + c*(15*RSTR);
                    #pragma unroll
                    for (int k = 0; k < 8; k++) {
                        if (ry + 2*k < 15) d2[k*2*RSTR] = s2[k*2*WW];
                    }
                }
            } else {
                const float* src = vid + tj*3*HW;
                #pragma unroll
                for (int c = 0; c < 3; c++) {
                    #pragma unroll
                    for (int k = 0; k < 8; k++) {
                        int r = ry + 2*k;
                        if (r < 15) {
                            int y = min(ys + r, HH-1);
                            int x = min(xs + rx, WW-1);
                            region[ds*(3*15*RSTR) + (c*15 + r)*RSTR + rx] = src[c*HW + y*WW + x];
                        }
                    }
                }
            }
        }
    }
    __syncthreads();   /* s_sh complete (also covers private regions / qR later per-warp) */

    /* ---- query patch built from s_sh (identical clamping); Sum(q^2) ---- */
    float qsq_part = 0.f;
    {
        const int rbase = min(hi, 4);           /* hi - max(hi-4,0) */
        const int cbase = wi - max(wi0 - 4, 0); /* query col 0 within s_sh */
        #pragma unroll
        for (int k = 0; k < 6; k++) {
            int e = lane + 32*k;
            if (e < 168) {
                int row = e >> 3, px = e & 7;
                float val = 0.f;
                if (px < 7) {
                    int c = row / 7, py = row - (row/7)*7;
                    val = s_sh[(c*15 + rbase + py)*SSTR + cbase + px];
                    qsq_part = fmaf(val, val, qsq_part);
                }
                qR[e] = val;
                qL[(row << 3) + ((px + 1) & 7)] = val;
            }
        }
    }
    #pragma unroll
    for (int off = 16; off; off >>= 1)
        qsq_part += __shfl_xor_sync(0xffffffffu, qsq_part, off);
    const float qs = qsq_part;
    __syncwarp();

    float d[9];
    #pragma unroll
    for (int j = 0; j < 9; j++) d[j] = FLT_MAX;

    if (lane < 27) {
        const int di = lane / 9, sy = lane - di*9;
        const int ys = meta[di*4 + 1];
        const int bh = meta[di*4 + 2];
        const int bw = meta[di*4 + 3];
        const int rowoff = min(max(bh - 4 + sy, 0), HH - 1) - ys;
        const int xsS = max(wi0 - 4, 0);
        const int xb  = (di == 1) ? xsS : max(bw - 4, 0);
        const int stride = (di == 1) ? SSTR : RSTR;
        const float* base = (di == 1) ? s_sh
                                      : region + (di == 0 ? 0 : 3*15*RSTR);
        const int xoff = max(bw - 4, 0) - xb;       /* 0 for private regions */
        const bool fastx = (bw >= 4) && (bw <= WW - 11);

        if (fastx) {
            u64 acc[9], sq2[8];
            #pragma unroll
            for (int s = 0; s < 9; s++) acc[s] = 0ull;
            #pragma unroll
            for (int p = 0; p < 8; p++) sq2[p] = 0ull;

            const float* pb = base + rowoff*stride + xoff;
            #pragma unroll
            for (int c = 0; c < 3; c++) {
                #pragma unroll
                for (int py = 0; py < 7; py++) {
                    const u64* vrow = (const u64*)(pb + (c*15 + py)*stride);
                    const ulonglong2* qrv = (const ulonglong2*)(qR + (c*7 + py)*QSTR);
                    const ulonglong2* qlv = (const ulonglong2*)(qL + (c*7 + py)*QSTR);
                    u64 ve[8];
                    #pragma unroll
                    for (int p = 0; p < 8; p++) ve[p] = vrow[p];
                    ulonglong2 qa = qrv[0], qb = qrv[1];
                    ulonglong2 qc = qlv[0], qd = qlv[1];
                    u64 qe[4] = {qa.x, qa.y, qb.x, qb.y};
                    u64 qo[4] = {qc.x, qc.y, qd.x, qd.y};

                    #pragma unroll
                    for (int j = 0; j < 4; j++) {
                        #pragma unroll
                        for (int e2 = 0; e2 < 5; e2++)      /* sx = 0,2,4,6,8 */
                            fma2(acc[2*e2], qe[j], ve[e2 + j]);
                        #pragma unroll
                        for (int o = 0; o < 4; o++)         /* sx = 1,3,5,7 */
                            fma2(acc[2*o + 1], qo[j], ve[o + j]);
                    }
                    #pragma unroll
                    for (int p = 0; p < 8; p++) fma2(sq2[p], ve[p], ve[p]);
                }
            }

            float col[15];
            {
                float lo, hiv;
                #pragma unroll
                for (int p = 0; p < 7; p++) { upk2(sq2[p], lo, hiv); col[2*p] = lo; col[2*p+1] = hiv; }
                upk2(sq2[7], lo, hiv); col[14] = lo;
            }
            float pre[16]; pre[0] = 0.f;
            #pragma unroll
            for (int j = 0; j < 15; j++) pre[j+1] = pre[j] + col[j];
            #pragma unroll
            for (int sx = 0; sx < 9; sx++) {
                float alo, ahi; upk2(acc[sx], alo, ahi);
                float qv = alo + ahi;
                float vs = pre[sx+7] - pre[sx];
                d[sx] = fmaf(-2.f, qv, qs + vs);
            }
        } else {
            /* rare x-border path */
            #pragma unroll
            for (int sx = 0; sx < 9; sx++) {
                int co = min(max(bw - 4 + sx, 0), WW - 1) - xb;
                float a = 0.f;
                for (int c = 0; c < 3; c++) {
                    for (int py = 0; py < 7; py++) {
                        const float* row = base + (c*15 + rowoff + py)*stride + co;
                        const float* qrow = qR + (c*7 + py)*QSTR;
                        #pragma unroll
                        for (int px = 0; px < 7; px++) {
                            float t = qrow[px] - row[px];
                            a = fmaf(t, t, a);
                        }
                    }
                }
                d[sx] = a;
            }
        }
    }

    /* ---- top-10 via REDUX.MIN on monotone uint keys ---- */
    unsigned k[9];
    #pragma unroll
    for (int j = 0; j < 9; j++) k[j] = __float_as_uint(fmaxf(d[j], 0.f));

    float sumK = 0.f;
    unsigned need = KK;
    #pragma unroll 1
    while (need) {
        unsigned mloc = k[0];
        #pragma unroll
        for (int j = 1; j < 9; j++) mloc = min(mloc, k[j]);
        unsigned m = __reduce_min_sync(0xffffffffu, mloc);
        unsigned cl = 0;
        #pragma unroll
        for (int j = 0; j < 9; j++) {
            if (k[j] == m) { k[j] = 0xffffffffu; cl++; }
        }
        unsigned tot = __reduce_add_sync(0xffffffffu, cl);
        unsigned take = min(tot, need);
        sumK += __uint_as_float(m) * (float)take;
        need -= take;
    }
    if (lane == 0) atomicAdd(&g_accum, (double)sumK);

    /* ---- last-block finalize + reset ---- */
    __threadfence();
    __syncthreads();
    if (tid == 0) {
        unsigned prev = atomicAdd(&g_count, 1u);
        if (prev == gridDim.x - 1) {
            double s = atomicAdd(&g_accum, 0.0);
            float mean = (float)(s / ((double)NQ * (double)KK));
            for (int i = 0; i < out_size; i++) out[i] = mean;
            g_count = 0u;
            g_accum = 0.0;
            __threadfence();
        }
    }
}

extern "C" void kernel_launch(void* const* d_in, const int* in_sizes, int n_in,
                              void* d_out, int out_size) {
    const float* noisy = (const float*)d_in[0];
    /* d_in[1] = deno: dead */
    const float* fflow = (const float*)d_in[2];
    const float* bflow = (const float*)d_in[3];
    float* out = (float*)d_out;

    fused_kernel<<<NQ / WPB, 32 * WPB>>>(noisy, fflow, bflow, out, out_size);
}